// round 14
// baseline (speedup 1.0000x reference)
#include <cuda_runtime.h>
#include <math.h>

// predictor_interp2d: nearest-bot gather onto a 256x256 grid.
// Single-barrier design: fixed-radius tile pruning into PER-WARP segments
// (ballot-ordered compaction), half-warp 4x4-subtile refine (REDUX min),
// fused ballot + exact argmin. One __syncthreads total.
//
// Inputs: d_in[0] = R_pc [B=2,C=4,N=1024] f32 ; d_in[1] = XY_pc [B=2,2,N=1024] f32
// Output: R_grd [B,C,256,256] f32
//
// Exactness:
//  - Level 1 (16x16 tile): keep p iff d(tile_center,p) <= RFIX. A-posteriori
//    per-cell check best + ||g||^2 <= (RFIX - R_TILE - 5e-3)^2 proves the RFIX
//    disk contained every possible winner/tie (triangle inequality, margins >>
//    fp noise); failing cells do an exact full gmem scan.
//  - Level 2 (4x4 subtile): keep p iff d(sc,p) <= min_list d(sc,q) + 2*R_SUB
//    + 1e-3 (standard bound over the whole candidate list).
//  - Final argmin uses the reference-rounded formula
//      pn2 = rn(x*x)+rn(y*y); dot = fmaf(gy,y,rn(gx*x)); d2 = fmaf(-2,dot,pn2)
//    scanned in ascending point order with strict '<' (first-min tie-break),
//    bit-exact vs the JAX reference. Segment overflow -> exact full scan.

#define GH 256
#define GW 256
#define NPTS 1024
#define NCH 4
#define TILE 16
#define TPB 256
#define SEGCAP 32
#define RFIX   0.12f
#define RTILE  0.041434f         // 7.5*sqrt(2)/256, rounded up
#define RSUB   0.008287f         // 1.5*sqrt(2)/256, rounded up
#define CHK2   0.005411f         // (RFIX - RTILE - 5e-3)^2, rounded DOWN (conservative)

__global__ void __launch_bounds__(TPB, 4)
nn_seg2_kernel(const float* __restrict__ R,
               const float* __restrict__ XY,
               float* __restrict__ out)
{
    __shared__ float4 seg[8 * SEGCAP];   // per-warp segments (x,y,pn2,idx), asc n
    __shared__ int s_cnt[8];

    const int tid  = threadIdx.x;
    const int lane = tid & 31;
    const int warp = tid >> 5;

    const int b    = blockIdx.x >> 8;
    const int tile = blockIdx.x & 255;
    const int r0   = (tile >> 4) * TILE;
    const int c0   = (tile & 15) * TILE;

    const float* xp = XY + b * (2 * NPTS);
    const float* yp = xp + NPTS;

    // ---- level 1: own 4 points in registers, fixed-radius flag ----
    const float4 xv = *(const float4*)(xp + 4 * tid);
    const float4 yv = *(const float4*)(yp + 4 * tid);
    const float px[4] = { xv.x, xv.y, xv.z, xv.w };
    const float py[4] = { yv.x, yv.y, yv.z, yv.w };

    const float gcx = ((float)c0 + 8.0f) * (1.0f / GW);
    const float gcy = ((float)r0 + 8.0f) * (1.0f / GH);

    bool keep[4];
#pragma unroll
    for (int i = 0; i < 4; ++i) {
        const float dx = gcx - px[i];
        const float dy = gcy - py[i];
        keep[i] = (__fmaf_rn(dy, dy, dx * dx) <= RFIX * RFIX);
    }

    // ---- ballot-ordered warp compaction (ascending index (tid,i)) ----
    unsigned bal[4];
#pragma unroll
    for (int i = 0; i < 4; ++i)
        bal[i] = __ballot_sync(0xffffffffu, keep[i]);

    const unsigned lt = (1u << lane) - 1u;
    int pos = 0, cnt_w = 0;
#pragma unroll
    for (int i = 0; i < 4; ++i) {
        pos   += __popc(bal[i] & lt);
        cnt_w += __popc(bal[i]);
    }
    if (lane == 0) s_cnt[warp] = cnt_w;

    {
        float4* wseg = seg + warp * SEGCAP;
        const int nbase = 4 * tid;
#pragma unroll
        for (int i = 0; i < 4; ++i) {
            if (keep[i]) {
                if (pos < SEGCAP) {
                    const float x = px[i], y = py[i];
                    const float pn2 = __fadd_rn(__fmul_rn(x, x), __fmul_rn(y, y));
                    wseg[pos] = make_float4(x, y, pn2, __int_as_float(nbase + i));
                }
                ++pos;
            }
        }
    }
    __syncthreads();                          // the ONLY block barrier

    int cnt[8];
    bool ovf = false;
#pragma unroll
    for (int t = 0; t < 8; ++t) { cnt[t] = s_cnt[t]; ovf |= (cnt[t] > SEGCAP); }

    // ---- subtile geometry: half-warp per 4x4 subtile ----
    const int s = tid >> 4;                   // subtile 0..15
    const int j = tid & 15;
    const unsigned gmask = (tid & 16) ? 0xFFFF0000u : 0x0000FFFFu;
    const int sr = (s >> 2) * 4;
    const int sc = (s & 3) * 4;
    const int r = r0 + sr + (j >> 2);
    const int c = c0 + sc + (j & 3);
    const float gx = ((float)c + 0.5f) * (1.0f / GW);
    const float gy = ((float)r + 0.5f) * (1.0f / GH);

    float best = 3.4e38f;
    int   bn = 0;
    bool  need_full = ovf;

    if (!ovf) {
        const float scx = ((float)(c0 + sc) + 2.0f) * (1.0f / GW);
        const float scy = ((float)(r0 + sr) + 2.0f) * (1.0f / GH);

        // ---- pass 1: min dist(subtile center, candidate) over all segments ----
        float d2e[8];
        float sm = 3.0e38f;
#pragma unroll
        for (int t = 0; t < 8; ++t) {
            float d2v = 3.0e38f;
            if (j < cnt[t]) {                 // lower half of segment (e = j)
                const float4 q = seg[t * SEGCAP + j];
                const float dx = scx - q.x;
                const float dy = scy - q.y;
                d2v = __fmaf_rn(dy, dy, dx * dx);
            }
            d2e[t] = d2v;
            sm = fminf(sm, d2v);
            if (cnt[t] > 16) {                // rare upper half (e = 16 + j)
                if (16 + j < cnt[t]) {
                    const float4 q = seg[t * SEGCAP + 16 + j];
                    const float dx = scx - q.x;
                    const float dy = scy - q.y;
                    sm = fminf(sm, __fmaf_rn(dy, dy, dx * dx));
                }
            }
        }
        // half-warp min via REDUX on order-preserving uint view (sm >= 0)
        sm = __uint_as_float(__reduce_min_sync(gmask, __float_as_uint(sm)));
        const float Ts = sqrtf(sm) + 2.0f * RSUB + 1.0e-3f;
        const float th2 = Ts * Ts;

        // ---- pass 2: ballot survivors per segment, exact argmin inline ----
        // (segments ascending, element ascending => ascending point index)
#pragma unroll
        for (int t = 0; t < 8; ++t) {
            const bool f = (j < cnt[t]) && (d2e[t] <= th2);
            unsigned mb = __ballot_sync(0xffffffffu, f) & gmask;
            while (mb) {
                const int bit = __ffs(mb) - 1;
                mb &= mb - 1u;
                const float4 q = seg[t * SEGCAP + (bit & 15)];
                const float dot = __fmaf_rn(gy, q.y, __fmul_rn(gx, q.x));
                const float d2  = __fmaf_rn(-2.0f, dot, q.z);
                if (d2 < best) { best = d2; bn = __float_as_int(q.w); }
            }
            if (cnt[t] > 16) {                // rare upper half
                float d2o = 3.0e38f;
                const bool v2 = (16 + j < cnt[t]);
                if (v2) {
                    const float4 q = seg[t * SEGCAP + 16 + j];
                    const float dx = scx - q.x;
                    const float dy = scy - q.y;
                    d2o = __fmaf_rn(dy, dy, dx * dx);
                }
                unsigned mo = __ballot_sync(0xffffffffu, v2 && (d2o <= th2)) & gmask;
                while (mo) {
                    const int bit = __ffs(mo) - 1;
                    mo &= mo - 1u;
                    const float4 q = seg[t * SEGCAP + 16 + (bit & 15)];
                    const float dot = __fmaf_rn(gy, q.y, __fmul_rn(gx, q.x));
                    const float d2  = __fmaf_rn(-2.0f, dot, q.z);
                    if (d2 < best) { best = d2; bn = __float_as_int(q.w); }
                }
            }
        }

        // ---- a-posteriori exactness check (sqrt-free, conservative) ----
        const float g2 = __fmaf_rn(gy, gy, gx * gx);
        need_full = (best + g2 > CHK2);
    }

    if (need_full) {                          // exact full scan (vanishingly rare)
        best = 3.4e38f; bn = 0;
        for (int n = 0; n < NPTS; ++n) {
            const float x = __ldg(xp + n);
            const float y = __ldg(yp + n);
            const float pn2 = __fadd_rn(__fmul_rn(x, x), __fmul_rn(y, y));
            const float dot = __fmaf_rn(gy, y, __fmul_rn(gx, x));
            const float d2  = __fmaf_rn(-2.0f, dot, pn2);
            if (d2 < best) { best = d2; bn = n; }
        }
    }

    // ---- gather channels + store ----
    const float* Rb = R + b * (NCH * NPTS);
    const int g = r * GW + c;
#pragma unroll
    for (int ch = 0; ch < NCH; ++ch)
        out[(b * NCH + ch) * (GH * GW) + g] = __ldg(Rb + ch * NPTS + bn);
}

extern "C" void kernel_launch(void* const* d_in, const int* in_sizes, int n_in,
                              void* d_out, int out_size)
{
    const float* R  = (const float*)d_in[0];
    const float* XY = (const float*)d_in[1];
    nn_seg2_kernel<<<512, TPB>>>(R, XY, (float*)d_out);
}

// round 15
// speedup vs baseline: 1.0037x; 1.0037x over previous
#include <cuda_runtime.h>
#include <math.h>

// predictor_interp2d: nearest-bot gather onto a 256x256 grid.
// Single-barrier design: fixed-radius tile pruning into PER-WARP segments
// (ballot-ordered compaction), half-warp 4x4-subtile refine (REDUX min),
// fused ballot + exact argmin. One __syncthreads total.
//
// Inputs: d_in[0] = R_pc [B=2,C=4,N=1024] f32 ; d_in[1] = XY_pc [B=2,2,N=1024] f32
// Output: R_grd [B,C,256,256] f32
//
// Exactness:
//  - Level 1 (16x16 tile): keep p iff d(tile_center,p) <= RFIX. A-posteriori
//    per-cell check best + ||g||^2 <= (RFIX - R_TILE - 5e-3)^2 proves the RFIX
//    disk contained every possible winner/tie (triangle inequality, margins >>
//    fp noise); failing cells do an exact full gmem scan.
//  - Level 2 (4x4 subtile): keep p iff d(sc,p) <= min_list d(sc,q) + 2*R_SUB
//    + 1e-3 (standard bound over the whole candidate list).
//  - Final argmin uses the reference-rounded formula
//      pn2 = rn(x*x)+rn(y*y); dot = fmaf(gy,y,rn(gx*x)); d2 = fmaf(-2,dot,pn2)
//    scanned in ascending point order with strict '<' (first-min tie-break),
//    bit-exact vs the JAX reference. Segment overflow -> exact full scan.

#define GH 256
#define GW 256
#define NPTS 1024
#define NCH 4
#define TILE 16
#define TPB 256
#define SEGCAP 32
#define RFIX   0.12f
#define RTILE  0.041434f         // 7.5*sqrt(2)/256, rounded up
#define RSUB   0.008287f         // 1.5*sqrt(2)/256, rounded up
#define CHK2   0.005411f         // (RFIX - RTILE - 5e-3)^2, rounded DOWN (conservative)

__global__ void __launch_bounds__(TPB, 6)
nn_seg3_kernel(const float* __restrict__ R,
               const float* __restrict__ XY,
               float* __restrict__ out)
{
    __shared__ float4 seg[8 * SEGCAP];   // per-warp segments (x,y,pn2,idx), asc n
    __shared__ int s_cnt[8];

    const int tid  = threadIdx.x;
    const int lane = tid & 31;
    const int warp = tid >> 5;

    const int b    = blockIdx.x >> 8;
    const int tile = blockIdx.x & 255;
    const int r0   = (tile >> 4) * TILE;
    const int c0   = (tile & 15) * TILE;

    const float* xp = XY + b * (2 * NPTS);
    const float* yp = xp + NPTS;

    // ---- level 1: own 4 points in registers, fixed-radius flag ----
    const float4 xv = *(const float4*)(xp + 4 * tid);
    const float4 yv = *(const float4*)(yp + 4 * tid);
    const float px[4] = { xv.x, xv.y, xv.z, xv.w };
    const float py[4] = { yv.x, yv.y, yv.z, yv.w };

    const float gcx = ((float)c0 + 8.0f) * (1.0f / GW);
    const float gcy = ((float)r0 + 8.0f) * (1.0f / GH);

    bool keep[4];
#pragma unroll
    for (int i = 0; i < 4; ++i) {
        const float dx = gcx - px[i];
        const float dy = gcy - py[i];
        keep[i] = (__fmaf_rn(dy, dy, dx * dx) <= RFIX * RFIX);
    }

    // ---- ballot-ordered warp compaction (ascending index (tid,i)) ----
    unsigned bal[4];
#pragma unroll
    for (int i = 0; i < 4; ++i)
        bal[i] = __ballot_sync(0xffffffffu, keep[i]);

    const unsigned lt = (1u << lane) - 1u;
    int pos = 0, cnt_w = 0;
#pragma unroll
    for (int i = 0; i < 4; ++i) {
        pos   += __popc(bal[i] & lt);
        cnt_w += __popc(bal[i]);
    }
    if (lane == 0) s_cnt[warp] = cnt_w;

    {
        float4* wseg = seg + warp * SEGCAP;
        const int nbase = 4 * tid;
#pragma unroll
        for (int i = 0; i < 4; ++i) {
            if (keep[i]) {
                if (pos < SEGCAP) {
                    const float x = px[i], y = py[i];
                    const float pn2 = __fadd_rn(__fmul_rn(x, x), __fmul_rn(y, y));
                    wseg[pos] = make_float4(x, y, pn2, __int_as_float(nbase + i));
                }
                ++pos;
            }
        }
    }
    __syncthreads();                          // the ONLY block barrier

    int cnt[8];
    bool ovf = false, any_hi = false;
#pragma unroll
    for (int t = 0; t < 8; ++t) {
        cnt[t] = s_cnt[t];
        ovf    |= (cnt[t] > SEGCAP);
        any_hi |= (cnt[t] > 16);
    }

    // ---- subtile geometry: half-warp per 4x4 subtile ----
    const int s = tid >> 4;                   // subtile 0..15
    const int j = tid & 15;
    const unsigned gmask = (tid & 16) ? 0xFFFF0000u : 0x0000FFFFu;
    const int sr = (s >> 2) * 4;
    const int sc = (s & 3) * 4;
    const int r = r0 + sr + (j >> 2);
    const int c = c0 + sc + (j & 3);
    const float gx = ((float)c + 0.5f) * (1.0f / GW);
    const float gy = ((float)r + 0.5f) * (1.0f / GH);

    // output addressing off the bn-dependent tail
    const float* Rb = R + b * (NCH * NPTS);
    float* ob = out + b * (NCH * GH * GW) + r * GW + c;

    float best = 3.4e38f;
    int   bn = 0;
    bool  need_full = ovf;

    if (!ovf) {
        const float scx = ((float)(c0 + sc) + 2.0f) * (1.0f / GW);
        const float scy = ((float)(r0 + sr) + 2.0f) * (1.0f / GH);

        // ---- pass 1: min dist(subtile center, candidate) over all segments ----
        float d2e[8];
        float sm = 3.0e38f;
#pragma unroll
        for (int t = 0; t < 8; ++t) {
            float d2v = 3.0e38f;
            if (j < cnt[t]) {
                const float4 q = seg[t * SEGCAP + j];
                const float dx = scx - q.x;
                const float dy = scy - q.y;
                d2v = __fmaf_rn(dy, dy, dx * dx);
            }
            d2e[t] = d2v;
            sm = fminf(sm, d2v);
        }
        if (any_hi) {                         // rare: upper halves exist
#pragma unroll
            for (int t = 0; t < 8; ++t) {
                if (16 + j < cnt[t]) {
                    const float4 q = seg[t * SEGCAP + 16 + j];
                    const float dx = scx - q.x;
                    const float dy = scy - q.y;
                    sm = fminf(sm, __fmaf_rn(dy, dy, dx * dx));
                }
            }
        }
        // half-warp min via REDUX on order-preserving uint view (sm >= 0)
        sm = __uint_as_float(__reduce_min_sync(gmask, __float_as_uint(sm)));
        const float Ts = sqrtf(sm) + 2.0f * RSUB + 1.0e-3f;
        const float th2 = Ts * Ts;

        // ---- pass 2: ballot survivors per segment, exact argmin inline ----
        // (segments ascending, element ascending => ascending point index)
#pragma unroll
        for (int t = 0; t < 8; ++t) {
            const bool f = (j < cnt[t]) && (d2e[t] <= th2);
            unsigned mb = __ballot_sync(0xffffffffu, f) & gmask;
            while (mb) {
                const int bit = __ffs(mb) - 1;
                mb &= mb - 1u;
                const float4 q = seg[t * SEGCAP + (bit & 15)];
                const float dot = __fmaf_rn(gy, q.y, __fmul_rn(gx, q.x));
                const float d2  = __fmaf_rn(-2.0f, dot, q.z);
                if (d2 < best) { best = d2; bn = __float_as_int(q.w); }
            }
            if (any_hi && cnt[t] > 16) {      // rare upper half
                float d2o = 3.0e38f;
                const bool v2 = (16 + j < cnt[t]);
                if (v2) {
                    const float4 q = seg[t * SEGCAP + 16 + j];
                    const float dx = scx - q.x;
                    const float dy = scy - q.y;
                    d2o = __fmaf_rn(dy, dy, dx * dx);
                }
                unsigned mo = __ballot_sync(0xffffffffu, v2 && (d2o <= th2)) & gmask;
                while (mo) {
                    const int bit = __ffs(mo) - 1;
                    mo &= mo - 1u;
                    const float4 q = seg[t * SEGCAP + 16 + (bit & 15)];
                    const float dot = __fmaf_rn(gy, q.y, __fmul_rn(gx, q.x));
                    const float d2  = __fmaf_rn(-2.0f, dot, q.z);
                    if (d2 < best) { best = d2; bn = __float_as_int(q.w); }
                }
            }
        }

        // ---- a-posteriori exactness check (sqrt-free, conservative) ----
        const float g2 = __fmaf_rn(gy, gy, gx * gx);
        need_full = (best + g2 > CHK2);
    }

    if (need_full) {                          // exact full scan (vanishingly rare)
        best = 3.4e38f; bn = 0;
        for (int n = 0; n < NPTS; ++n) {
            const float x = __ldg(xp + n);
            const float y = __ldg(yp + n);
            const float pn2 = __fadd_rn(__fmul_rn(x, x), __fmul_rn(y, y));
            const float dot = __fmaf_rn(gy, y, __fmul_rn(gx, x));
            const float d2  = __fmaf_rn(-2.0f, dot, pn2);
            if (d2 < best) { best = d2; bn = n; }
        }
    }

    // ---- gather channels + store (addresses precomputed) ----
#pragma unroll
    for (int ch = 0; ch < NCH; ++ch)
        ob[ch * (GH * GW)] = __ldg(Rb + ch * NPTS + bn);
}

extern "C" void kernel_launch(void* const* d_in, const int* in_sizes, int n_in,
                              void* d_out, int out_size)
{
    const float* R  = (const float*)d_in[0];
    const float* XY = (const float*)d_in[1];
    nn_seg3_kernel<<<512, TPB>>>(R, XY, (float*)d_out);
}